// round 10
// baseline (speedup 1.0000x reference)
#include <cuda_runtime.h>
#include <cuda_bf16.h>

// Gridding R8: parity-grid scratch (2 v4 REDs/point), 4 phases x 8 batches,
// two 32MB scratch buffers ping-ponged. Remap + re-zero of buffer K runs on a
// second (forked) stream concurrently with scatter of the next phase on the
// capture stream, hiding remap/memset (bandwidth-bound) behind the scatter
// (L2 atomic-op-slot-bound).

#define GRID_S    32
#define GRID_G    64
#define NPTS_LOG2 18
#define NB_PHASE  8
#define NPHASE    4
#define SCR_FLOATS (4 * NB_PHASE * (1 << NPTS_LOG2))   // 8M floats = 32MB

__device__ float g_scratchA[SCR_FLOATS];
__device__ float g_scratchB[SCR_FLOATS];

__device__ __forceinline__ void red_v4(float* p, float a, float b, float c, float d) {
    asm volatile("red.global.add.v4.f32 [%0], {%1, %2, %3, %4};"
                 :: "l"(p), "f"(a), "f"(b), "f"(c), "f"(d) : "memory");
}

__global__ __launch_bounds__(256)
void gridding_scatter_kernel(const float* __restrict__ pt,
                             float* __restrict__ scratch, int npts_phase)
{
    int i = blockIdx.x * blockDim.x + threadIdx.x;
    if (i >= npts_phase) return;

    // evict-first: points are read once; keep L2 for the scratch grids
    float x = __ldcs(&pt[3 * i + 0]) * (float)GRID_S;
    float y = __ldcs(&pt[3 * i + 1]) * (float)GRID_S;
    float z = __ldcs(&pt[3 * i + 2]) * (float)GRID_S;

    // drop points whose scaled coord-sum is exactly 0 (x32 scaling is exact)
    float m = ((x + y + z) != 0.0f) ? 1.0f : 0.0f;

    float fx = floorf(x), fy = floorf(y), fz = floorf(z);
    float dx = x - fx, dy = y - fy, dz = z - fz;   // fractions from UNCLIPPED floor

    int ix = min(max(__float2int_rn(fx) + GRID_S, 0), GRID_G - 2);
    int iy = min(max(__float2int_rn(fy) + GRID_S, 0), GRID_G - 2);
    int iz = min(max(__float2int_rn(fz) + GRID_S, 0), GRID_G - 2);

    float wx0 = (1.0f - dx) * m;
    float wx1 = dx * m;
    float wy0 = 1.0f - dy, wy1 = dy;
    float wz0 = 1.0f - dz, wz1 = dz;

    int b   = i >> NPTS_LOG2;            // batch-local within phase, [0,8)
    int phi = iy & 1;
    int zb  = iz & 1;
    int p   = iy >> 1;

    int gidx = phi * 2 + zb;
    int pos  = (ix << 12) + (p << 7) + 2 * (iz & ~1);          // 16B aligned
    float* base = scratch + (((gidx << 3) + b) << NPTS_LOG2) + pos;

    // lanes: {(y0,z0), (y1,z0), (y0,z1), (y1,z1)}
    float a0 = wy0 * wz0, a1 = wy1 * wz0, a2 = wy0 * wz1, a3 = wy1 * wz1;
    red_v4(base,        wx0 * a0, wx0 * a1, wx0 * a2, wx0 * a3);
    red_v4(base + 4096, wx1 * a0, wx1 * a1, wx1 * a2, wx1 * a3);   // x+1
}

__global__ __launch_bounds__(256)
void gridding_remap_kernel(float* __restrict__ out,
                           const float* __restrict__ scratch, int total)
{
    int idx = blockIdx.x * blockDim.x + threadIdx.x;
    if (idx >= total) return;

    int b = idx >> NPTS_LOG2;            // batch-local within phase
    int v = idx & ((1 << NPTS_LOG2) - 1);
    int z = v & 63;
    int y = (v >> 6) & 63;
    int x = v >> 12;

    float acc = 0.0f;

    // pairing phi=0 (iy even): always valid
    {
        int v0 = (x << 12) + ((y >> 1) << 7) + 2 * z + (y & 1);
        acc += scratch[(((0 << 3) + b) << NPTS_LOG2) + v0];
        if (v0 >= 2) acc += scratch[(((1 << 3) + b) << NPTS_LOG2) + v0 - 2];
    }
    // pairing phi=1 (iy odd): valid for 1 <= y <= 62
    if (y >= 1 && y <= 62) {
        int ym = y - 1;
        int v1 = (x << 12) + ((ym >> 1) << 7) + 2 * z + (ym & 1);
        acc += scratch[(((2 << 3) + b) << NPTS_LOG2) + v1];
        if (v1 >= 2) acc += scratch[(((3 << 3) + b) << NPTS_LOG2) + v1 - 2];
    }

    out[idx] = acc;
}

extern "C" void kernel_launch(void* const* d_in, const int* in_sizes, int n_in,
                              void* d_out, int out_size)
{
    const float* ptcloud = (const float*)d_in[0];
    float* out = (float*)d_out;

    int total_pts = in_sizes[0] / 3;             // 32 * 262144
    int pts_phase = total_pts / NPHASE;          // 8 * 262144
    int out_phase = out_size / NPHASE;           // 8 * 262144
    const size_t SBYTES = (size_t)SCR_FLOATS * sizeof(float);

    // one-time creation (happens on the eager correctness call, before capture)
    static cudaStream_t sR = nullptr;
    static cudaEvent_t evRoot, evEnd, evS[NPHASE], evBuf[NPHASE];
    if (sR == nullptr) {
        cudaStreamCreateWithFlags(&sR, cudaStreamNonBlocking);
        cudaEventCreateWithFlags(&evRoot, cudaEventDisableTiming);
        cudaEventCreateWithFlags(&evEnd,  cudaEventDisableTiming);
        for (int k = 0; k < NPHASE; k++) {
            cudaEventCreateWithFlags(&evS[k],   cudaEventDisableTiming);
            cudaEventCreateWithFlags(&evBuf[k], cudaEventDisableTiming);
        }
    }

    float *sA = nullptr, *sB = nullptr;
    cudaGetSymbolAddress((void**)&sA, g_scratchA);
    cudaGetSymbolAddress((void**)&sB, g_scratchB);
    float* bufs[2] = { sA, sB };

    const int threads = 256;
    int sblocks = (pts_phase + threads - 1) / threads;
    int rblocks = (out_phase + threads - 1) / threads;

    // stream 0 = capture stream. Fork sR off it.
    cudaMemsetAsync(sA, 0, SBYTES, 0);
    cudaEventRecord(evRoot, 0);
    cudaStreamWaitEvent(sR, evRoot, 0);
    cudaMemsetAsync(sB, 0, SBYTES, sR);          // overlaps scatter(0)
    cudaEventRecord(evBuf[1], sR);

    for (int ph = 0; ph < NPHASE; ph++) {
        float* buf = bufs[ph & 1];

        if (ph >= 1)
            cudaStreamWaitEvent(0, evBuf[ph], 0);   // buffer re-zeroed?
        gridding_scatter_kernel<<<sblocks, threads, 0, 0>>>(
            ptcloud + (size_t)ph * pts_phase * 3, buf, pts_phase);
        cudaEventRecord(evS[ph], 0);

        cudaStreamWaitEvent(sR, evS[ph], 0);
        gridding_remap_kernel<<<rblocks, threads, 0, sR>>>(
            out + (size_t)ph * out_phase, buf, out_phase);
        if (ph + 2 < NPHASE) {
            cudaMemsetAsync(buf, 0, SBYTES, sR);    // re-zero for phase ph+2
            cudaEventRecord(evBuf[ph + 2], sR);
        }
    }

    // join sR back into the capture stream
    cudaEventRecord(evEnd, sR);
    cudaStreamWaitEvent(0, evEnd, 0);
}

// round 12
// speedup vs baseline: 1.0002x; 1.0002x over previous
#include <cuda_runtime.h>
#include <cuda_bf16.h>

// Gridding R10: fused-phase pipeline. Each launch co-schedules three roles in
// one grid (interleaved by blockIdx so they share the SMs concurrently):
//   - scatter(phase ph)   -> buf[ph%3]       (2 v4 REDs/point, L2 RMW bound)
//   - remap(phase ph-1)   <- buf[(ph-1)%3]   (bandwidth)
//   - zero buf[(ph+1)%3]                     (bandwidth)
// Buffers are disjoint within a launch -> no intra-kernel sync needed.

#define GRID_S    32
#define GRID_G    64
#define NPTS_LOG2 18
#define NB_PHASE  8
#define NPHASE    4
#define SCR_FLOATS (4 * NB_PHASE * (1 << NPTS_LOG2))   // 8M floats = 32MB

__device__ float g_scr0[SCR_FLOATS];
__device__ float g_scr1[SCR_FLOATS];
__device__ float g_scr2[SCR_FLOATS];

#define SBLOCKS 8192   // scatter sub-blocks (2.1M pts / 256)
#define RBLOCKS 8192   // remap sub-blocks   (2.1M outs / 256)
#define ZBLOCKS 2048   // zero sub-blocks    (524288 threads x 4 float4 = 32MB)
#define GROUPS  2048   // grid = GROUPS * 9
#define ZTHREADS (ZBLOCKS * 256)

__device__ __forceinline__ void red_v4(float* p, float a, float b, float c, float d) {
    asm volatile("red.global.add.v4.f32 [%0], {%1, %2, %3, %4};"
                 :: "l"(p), "f"(a), "f"(b), "f"(c), "f"(d) : "memory");
}

__device__ __forceinline__ void do_scatter(const float* __restrict__ pt,
                                           float* __restrict__ scratch, int i)
{
    float x = __ldcs(&pt[3 * i + 0]) * (float)GRID_S;
    float y = __ldcs(&pt[3 * i + 1]) * (float)GRID_S;
    float z = __ldcs(&pt[3 * i + 2]) * (float)GRID_S;

    // drop points whose scaled coord-sum is exactly 0 (x32 scaling is exact)
    float m = ((x + y + z) != 0.0f) ? 1.0f : 0.0f;

    float fx = floorf(x), fy = floorf(y), fz = floorf(z);
    float dx = x - fx, dy = y - fy, dz = z - fz;   // fractions from UNCLIPPED floor

    int ix = min(max(__float2int_rn(fx) + GRID_S, 0), GRID_G - 2);
    int iy = min(max(__float2int_rn(fy) + GRID_S, 0), GRID_G - 2);
    int iz = min(max(__float2int_rn(fz) + GRID_S, 0), GRID_G - 2);

    float wx0 = (1.0f - dx) * m;
    float wx1 = dx * m;
    float wy0 = 1.0f - dy, wy1 = dy;
    float wz0 = 1.0f - dz, wz1 = dz;

    int b   = i >> NPTS_LOG2;            // batch-local within phase, [0,8)
    int phi = iy & 1;
    int zb  = iz & 1;
    int p   = iy >> 1;

    int gidx = phi * 2 + zb;
    int pos  = (ix << 12) + (p << 7) + 2 * (iz & ~1);          // 16B aligned
    float* base = scratch + (((gidx << 3) + b) << NPTS_LOG2) + pos;

    // lanes: {(y0,z0), (y1,z0), (y0,z1), (y1,z1)}
    float a0 = wy0 * wz0, a1 = wy1 * wz0, a2 = wy0 * wz1, a3 = wy1 * wz1;
    red_v4(base,        wx0 * a0, wx0 * a1, wx0 * a2, wx0 * a3);
    red_v4(base + 4096, wx1 * a0, wx1 * a1, wx1 * a2, wx1 * a3);   // x+1
}

__device__ __forceinline__ void do_remap(float* __restrict__ out,
                                         const float* __restrict__ scratch, int idx)
{
    int b = idx >> NPTS_LOG2;            // batch-local within phase
    int v = idx & ((1 << NPTS_LOG2) - 1);
    int z = v & 63;
    int y = (v >> 6) & 63;
    int x = v >> 12;

    float acc = 0.0f;

    // pairing phi=0 (iy even): always valid
    {
        int v0 = (x << 12) + ((y >> 1) << 7) + 2 * z + (y & 1);
        acc += __ldcg(&scratch[((0 * 8 + b) << NPTS_LOG2) + v0]);
        if (v0 >= 2) acc += __ldcg(&scratch[((1 * 8 + b) << NPTS_LOG2) + v0 - 2]);
    }
    // pairing phi=1 (iy odd): valid for 1 <= y <= 62
    if (y >= 1 && y <= 62) {
        int ym = y - 1;
        int v1 = (x << 12) + ((ym >> 1) << 7) + 2 * z + (ym & 1);
        acc += __ldcg(&scratch[((2 * 8 + b) << NPTS_LOG2) + v1]);
        if (v1 >= 2) acc += __ldcg(&scratch[((3 * 8 + b) << NPTS_LOG2) + v1 - 2]);
    }

    __stcs(&out[idx], acc);              // stream out; don't pollute L2
}

__global__ __launch_bounds__(256)
void gridding_fused_kernel(const float* __restrict__ pt,          // scatter src (or null)
                           float* __restrict__ sbuf,              // scatter dst
                           float* __restrict__ out,               // remap dst (or null)
                           const float* __restrict__ rbuf,        // remap src
                           float4* __restrict__ zbuf)             // zero dst (or null)
{
    int grp = blockIdx.x / 9;
    int r   = blockIdx.x - grp * 9;
    int tid = threadIdx.x;

    if (r < 4) {
        if (pt == nullptr) return;
        int i = ((grp << 2) + r) * 256 + tid;          // [0, 2.1M)
        do_scatter(pt, sbuf, i);
    } else if (r < 8) {
        if (out == nullptr) return;
        int j = ((grp << 2) + (r - 4)) * 256 + tid;    // [0, 2.1M)
        do_remap(out, rbuf, j);
    } else {
        if (zbuf == nullptr) return;
        int k = grp * 256 + tid;                        // [0, 524288)
        float4 zero = make_float4(0.f, 0.f, 0.f, 0.f);
        #pragma unroll
        for (int mrep = 0; mrep < 4; mrep++)
            zbuf[k + mrep * ZTHREADS] = zero;           // coalesced, keep in L2
    }
}

extern "C" void kernel_launch(void* const* d_in, const int* in_sizes, int n_in,
                              void* d_out, int out_size)
{
    const float* ptcloud = (const float*)d_in[0];
    float* out = (float*)d_out;

    int total_pts = in_sizes[0] / 3;             // 32 * 262144
    int pts_phase = total_pts / NPHASE;          // 8 * 262144 = 2097152
    int out_phase = out_size / NPHASE;           // 2097152
    const size_t SBYTES = (size_t)SCR_FLOATS * sizeof(float);

    float *b0, *b1, *b2;
    cudaGetSymbolAddress((void**)&b0, g_scr0);
    cudaGetSymbolAddress((void**)&b1, g_scr1);
    cudaGetSymbolAddress((void**)&b2, g_scr2);
    float* bufs[3] = { b0, b1, b2 };

    // prologue: zero buffer for phase 0
    cudaMemsetAsync(b0, 0, SBYTES, 0);

    const int grid = GROUPS * 9;   // 18432 blocks

    for (int ph = 0; ph <= NPHASE; ph++) {
        const float* pt_ph = (ph < NPHASE) ? ptcloud + (size_t)ph * pts_phase * 3 : nullptr;
        float*  sb   = bufs[ph % 3];
        float*  o_ph = (ph >= 1) ? out + (size_t)(ph - 1) * out_phase : nullptr;
        const float* rb = bufs[(ph + 2) % 3];            // (ph-1) mod 3
        float4* zb   = (ph + 1 < NPHASE) ? (float4*)bufs[(ph + 1) % 3] : nullptr;

        gridding_fused_kernel<<<grid, 256>>>(pt_ph, sb, o_ph, rb, zb);
    }
}

// round 13
// speedup vs baseline: 1.1060x; 1.1057x over previous
#include <cuda_runtime.h>
#include <cuda_bf16.h>

// Gridding R12: serial R7 structure (2 phases x 16 batches, 64MB L2-resident
// scratch), scatter = 2 v4 REDs/point (measured at the chip RED-op ceiling),
// remap rewritten as a p-loop sliding window with fully dense float2 loads:
// 0.625 LTS wavefronts/output vs ~1.06 before.

#define GRID_S    32
#define GRID_G    64
#define NPTS_LOG2 18
#define NB_PHASE  16
#define NPHASE    2
#define PCHUNK    8          // p-values per remap thread
#define NCHUNK    4          // 32 / PCHUNK

// 4 grids x 16 batches x 2^18 floats = 64 MB scratch (reused across phases)
__device__ float g_scratch[4 * NB_PHASE * (1 << NPTS_LOG2)];

__device__ __forceinline__ void red_v4(float* p, float a, float b, float c, float d) {
    asm volatile("red.global.add.v4.f32 [%0], {%1, %2, %3, %4};"
                 :: "l"(p), "f"(a), "f"(b), "f"(c), "f"(d) : "memory");
}

__global__ __launch_bounds__(256)
void gridding_scatter_kernel(const float* __restrict__ pt,
                             float* __restrict__ scratch, int npts_phase)
{
    int i = blockIdx.x * blockDim.x + threadIdx.x;
    if (i >= npts_phase) return;

    // evict-first: points are read once; keep L2 for the scratch grids
    float x = __ldcs(&pt[3 * i + 0]) * (float)GRID_S;
    float y = __ldcs(&pt[3 * i + 1]) * (float)GRID_S;
    float z = __ldcs(&pt[3 * i + 2]) * (float)GRID_S;

    // drop points whose scaled coord-sum is exactly 0 (x32 scaling is exact)
    float m = ((x + y + z) != 0.0f) ? 1.0f : 0.0f;

    float fx = floorf(x), fy = floorf(y), fz = floorf(z);
    float dx = x - fx, dy = y - fy, dz = z - fz;   // fractions from UNCLIPPED floor

    int ix = min(max(__float2int_rn(fx) + GRID_S, 0), GRID_G - 2);
    int iy = min(max(__float2int_rn(fy) + GRID_S, 0), GRID_G - 2);
    int iz = min(max(__float2int_rn(fz) + GRID_S, 0), GRID_G - 2);

    float wx0 = (1.0f - dx) * m;
    float wx1 = dx * m;
    float wy0 = 1.0f - dy, wy1 = dy;
    float wz0 = 1.0f - dz, wz1 = dz;

    int b   = i >> NPTS_LOG2;            // batch-local within phase, [0,16)
    int phi = iy & 1;
    int zb  = iz & 1;
    int p   = iy >> 1;

    int gidx = phi * 2 + zb;
    int pos  = (ix << 12) + (p << 7) + 2 * (iz & ~1);          // 16B aligned
    float* base = scratch + ((gidx * NB_PHASE + b) << NPTS_LOG2) + pos;

    // lanes: {(y0,z0), (y1,z0), (y0,z1), (y1,z1)}
    float a0 = wy0 * wz0, a1 = wy1 * wz0, a2 = wy0 * wz1, a3 = wy1 * wz1;
    red_v4(base,        wx0 * a0, wx0 * a1, wx0 * a2, wx0 * a3);
    red_v4(base + 4096, wx1 * a0, wx1 * a1, wx1 * a2, wx1 * a3);   // x+1
}

// Sliding-window remap. Thread = (b, x, z, chunk h); loops p over PCHUNK
// values producing outputs y=2p and y=2p+1 at fixed (x,z). Dense float2 loads:
//   g0[x,p,2z+cy]   : out(2p+cy) direct term
//   g1[x,p,2z-2+cy] : z-shifted grid (z=0 -> always-zero slots 126/127)
//   g2[x,p,2z+cy]   : odd-y pairing; out(2p+1) uses C.x, out(2p) uses Cprev.y
//   g3[x,p,2z-2+cy] : odd-y + z-shift; same window, D
// p=31 blocks of g2/g3 are never written (odd iy<=61) -> reading them adds 0.
__global__ __launch_bounds__(256)
void gridding_remap_kernel(float* __restrict__ out,
                           const float* __restrict__ scratch)
{
    int t = blockIdx.x * blockDim.x + threadIdx.x;
    int z = t & 63;
    int x = (t >> 6) & 63;
    int h = (t >> 12) & (NCHUNK - 1);
    int b = t >> 14;                     // [0, NB_PHASE)

    const float* g0 = scratch + ((0 * NB_PHASE + b) << NPTS_LOG2) + (x << 12);
    const float* g1 = scratch + ((1 * NB_PHASE + b) << NPTS_LOG2) + (x << 12);
    const float* g2 = scratch + ((2 * NB_PHASE + b) << NPTS_LOG2) + (x << 12);
    const float* g3 = scratch + ((3 * NB_PHASE + b) << NPTS_LOG2) + (x << 12);

    int qA = 2 * z;
    int qB = (z >= 1) ? (2 * z - 2) : 126;   // 126/127 are never-written (zero)

    int p0 = h * PCHUNK;
    float2 Cp, Dp;
    if (p0 == 0) {
        Cp = make_float2(0.f, 0.f);
        Dp = make_float2(0.f, 0.f);
    } else {
        Cp = *(const float2*)&g2[((p0 - 1) << 7) + qA];
        Dp = *(const float2*)&g3[((p0 - 1) << 7) + qB];
    }

    float* o = out + (b << NPTS_LOG2) + (x << 12) + z;

    #pragma unroll
    for (int p = p0; p < p0 + PCHUNK; p++) {
        float2 A = *(const float2*)&g0[(p << 7) + qA];
        float2 B = *(const float2*)&g1[(p << 7) + qB];
        float2 C = *(const float2*)&g2[(p << 7) + qA];
        float2 D = *(const float2*)&g3[(p << 7) + qB];

        float o0 = A.x + B.x + Cp.y + Dp.y;   // y = 2p
        float o1 = A.y + B.y + C.x  + D.x;    // y = 2p+1
        o[(2 * p)     << 6] = o0;
        o[(2 * p + 1) << 6] = o1;

        Cp = C;  Dp = D;
    }
}

extern "C" void kernel_launch(void* const* d_in, const int* in_sizes, int n_in,
                              void* d_out, int out_size)
{
    const float* ptcloud = (const float*)d_in[0];
    float* out = (float*)d_out;

    int total_pts = in_sizes[0] / 3;            // 32 * 262144
    int pts_phase = total_pts / NPHASE;         // 16 * 262144
    int out_phase = out_size / NPHASE;          // 16 * 262144

    void* scratch_ptr = nullptr;
    cudaGetSymbolAddress(&scratch_ptr, g_scratch);

    const int threads = 256;
    int sblocks = (pts_phase + threads - 1) / threads;
    // remap threads: NB_PHASE * 64(x) * 64(z) * NCHUNK
    int rthreads = NB_PHASE * 64 * 64 * NCHUNK;
    int rblocks = rthreads / threads;

    for (int ph = 0; ph < NPHASE; ph++) {
        cudaMemsetAsync(scratch_ptr, 0, sizeof(g_scratch), 0);
        gridding_scatter_kernel<<<sblocks, threads>>>(
            ptcloud + (size_t)ph * pts_phase * 3, (float*)scratch_ptr, pts_phase);
        gridding_remap_kernel<<<rblocks, threads>>>(
            out + (size_t)ph * out_phase, (const float*)scratch_ptr);
    }
}